// round 12
// baseline (speedup 1.0000x reference)
#include <cuda_runtime.h>

#define N_SRC 100000
#define N_MID 20000
#define N_OUT 5000
#define E1_N  20000
#define E2_N  20000
#define D_IN  64
#define D_H   64
#define D_EF  32

// Scratch (device globals — no allocations allowed)
__device__ float g_sum1[N_MID * D_H];   // layer-1 scatter sums, then normalized h_mid (in place)
__device__ float g_cnt1[N_MID];
__device__ float g_cnt2[N_OUT];

// ---------------- packed f32x2 helpers ----------------
__device__ __forceinline__ void ffma2(unsigned long long& d, unsigned long long a, unsigned long long b) {
    asm("fma.rn.f32x2 %0, %1, %2, %0;" : "+l"(d) : "l"(a), "l"(b));
}
__device__ __forceinline__ unsigned long long pack2(float x) {
    unsigned long long r;
    asm("mov.b64 %0, {%1, %1};" : "=l"(r) : "r"(__float_as_uint(x)));
    return r;
}

// ---------------- zero scratch + output ----------------
__global__ void zero_kernel(float* __restrict__ out) {
    int t = blockIdx.x * blockDim.x + threadIdx.x;
    if (t < N_MID * D_H) g_sum1[t] = 0.f;
    if (t < N_MID)       g_cnt1[t] = 0.f;
    if (t < N_OUT)       g_cnt2[t] = 0.f;
    if (t < N_OUT * D_H) out[t]    = 0.f;
}

// ---------------- degree counts (both layers) ----------------
__global__ void count_kernel(const int* __restrict__ dst1, const int* __restrict__ dst2) {
    int t = blockIdx.x * blockDim.x + threadIdx.x;
    if (t < E1_N)              atomicAdd(&g_cnt1[dst1[t]], 1.0f);
    else if (t < E1_N + E2_N)  atomicAdd(&g_cnt2[dst2[t - E1_N]], 1.0f);
}

// ---------------- fused edge kernel ----------------
// msg[e, o] = sum_i h[src[e], i] * ( b[i*64+o] + sum_f ef[e,f] * W[f, i*64+o] )
// CTA: 128 edges x 32 outputs (o-half by blockIdx.y). atomicAdd into accum[dst[e]].
template <int LAYER>
__global__ void __launch_bounds__(128, 4) edge_kernel(
    const float* __restrict__ hfeat_arg,   // layer1: in_feat; layer2: unused
    const float* __restrict__ efeat,       // [E, 32]
    const float* __restrict__ W,           // [32, 4096]
    const float* __restrict__ bias,        // [4096]
    const int*   __restrict__ src,
    const int*   __restrict__ dst,
    int E,
    float* __restrict__ accum_arg)         // layer2: d_out; layer1: unused
{
    __shared__ float hs[64 * 129];  // transposed: hs[i*129 + edge], conflict-free reads
    __shared__ float ws[33 * 36];   // per-i slice: rows f=0..31 of W, row 32 = bias; stride 36

    const float* hfeat = (LAYER == 1) ? hfeat_arg : g_sum1;
    float* accum       = (LAYER == 1) ? g_sum1    : accum_arg;

    const int tid = threadIdx.x;
    const int e0  = blockIdx.x * 128;
    const int o0  = blockIdx.y * 32;
    const int e   = e0 + tid;
    const bool act = (e < E);

    // edge features -> registers (vectorized)
    float ef[32];
    {
        const float4* p = reinterpret_cast<const float4*>(efeat + (size_t)(act ? e : 0) * 32);
#pragma unroll
        for (int k = 0; k < 8; k++) {
            float4 v = p[k];
            ef[4 * k + 0] = v.x; ef[4 * k + 1] = v.y;
            ef[4 * k + 2] = v.z; ef[4 * k + 3] = v.w;
        }
    }

    // cooperative gather of source-node features, transposed into hs
#pragma unroll
    for (int k = 0; k < 16; k++) {
        int j  = tid + k * 128;      // 0..2047
        int r  = j >> 4;             // edge row within tile
        int c4 = j & 15;             // float4 index along feature dim
        int s  = (e0 + r < E) ? src[e0 + r] : 0;
        float4 v = reinterpret_cast<const float4*>(hfeat + (size_t)s * 64)[c4];
        int i = c4 * 4;
        hs[(i + 0) * 129 + r] = v.x;
        hs[(i + 1) * 129 + r] = v.y;
        hs[(i + 2) * 129 + r] = v.z;
        hs[(i + 3) * 129 + r] = v.w;
    }

    unsigned long long acc[16];
#pragma unroll
    for (int k = 0; k < 16; k++) acc[k] = 0ull;

    for (int i = 0; i < 64; i++) {
        __syncthreads();
        // stage W[:, i*64+o0 .. +31] and bias row (33 rows x 32 floats)
#pragma unroll
        for (int k = 0; k < 3; k++) {
            int j = tid + k * 128;
            if (j < 264) {
                int row = j >> 3, c4 = j & 7;
                float4 v;
                if (row < 32) v = reinterpret_cast<const float4*>(W + (size_t)row * 4096 + i * 64 + o0)[c4];
                else          v = reinterpret_cast<const float4*>(bias + i * 64 + o0)[c4];
                *reinterpret_cast<float4*>(&ws[row * 36 + c4 * 4]) = v;
            }
        }
        __syncthreads();

        float hi = hs[i * 129 + tid];

        unsigned long long t[16];
#pragma unroll
        for (int k = 0; k < 16; k++)
            t[k] = *reinterpret_cast<const unsigned long long*>(&ws[32 * 36 + 2 * k]);

#pragma unroll
        for (int f = 0; f < 32; f++) {
            unsigned long long efp = pack2(ef[f]);
            const float* wrow = &ws[f * 36];
#pragma unroll
            for (int k2 = 0; k2 < 8; k2++) {
                ulonglong2 w = *reinterpret_cast<const ulonglong2*>(wrow + 4 * k2);  // LDS.128 -> 2x b64
                ffma2(t[2 * k2 + 0], w.x, efp);
                ffma2(t[2 * k2 + 1], w.y, efp);
            }
        }

        unsigned long long hip = pack2(hi);
#pragma unroll
        for (int k = 0; k < 16; k++) ffma2(acc[k], t[k], hip);
    }

    if (act) {
        float* outp = accum + (size_t)dst[e] * 64 + o0;
#pragma unroll
        for (int k = 0; k < 16; k++) {
            float2 v = *reinterpret_cast<float2*>(&acc[k]);
            atomicAdd(outp + 2 * k + 0, v.x);
            atomicAdd(outp + 2 * k + 1, v.y);
        }
    }
}

// ---------------- normalize (mean) kernels ----------------
__global__ void normalize1_kernel() {
    int t = blockIdx.x * blockDim.x + threadIdx.x;
    if (t >= N_MID * D_H) return;
    float c = g_cnt1[t >> 6];
    float v = g_sum1[t] / fmaxf(c, 1.0f);
    g_sum1[t] = fmaxf(v, 0.0f);   // relu
}

__global__ void normalize2_kernel(float* __restrict__ out) {
    int t = blockIdx.x * blockDim.x + threadIdx.x;
    if (t >= N_OUT * D_H) return;
    float c = g_cnt2[t >> 6];
    out[t] = out[t] / fmaxf(c, 1.0f);
}

// ---------------- launch ----------------
extern "C" void kernel_launch(void* const* d_in, const int* in_sizes, int n_in,
                              void* d_out, int out_size) {
    const float* in_feat = (const float*)d_in[0];
    const float* ef1     = (const float*)d_in[1];
    const float* ef2     = (const float*)d_in[2];
    const float* W1      = (const float*)d_in[3];
    const float* b1      = (const float*)d_in[4];
    const float* W2      = (const float*)d_in[5];
    const float* b2      = (const float*)d_in[6];
    const int*   src1    = (const int*)d_in[7];
    const int*   dst1    = (const int*)d_in[8];
    const int*   src2    = (const int*)d_in[9];
    const int*   dst2    = (const int*)d_in[10];
    float* out = (float*)d_out;

    zero_kernel<<<(N_MID * D_H + 255) / 256, 256>>>(out);
    count_kernel<<<(E1_N + E2_N + 255) / 256, 256>>>(dst1, dst2);

    dim3 egrid1((E1_N + 127) / 128, 2);
    edge_kernel<1><<<egrid1, 128>>>(in_feat, ef1, W1, b1, src1, dst1, E1_N, nullptr);
    normalize1_kernel<<<(N_MID * D_H + 255) / 256, 256>>>();

    dim3 egrid2((E2_N + 127) / 128, 2);
    edge_kernel<2><<<egrid2, 128>>>(nullptr, ef2, W2, b2, src2, dst2, E2_N, out);
    normalize2_kernel<<<(N_OUT * D_H + 255) / 256, 256>>>(out);
}

// round 13
// speedup vs baseline: 1.0033x; 1.0033x over previous
#include <cuda_runtime.h>

#define N_SRC 100000
#define N_MID 20000
#define N_OUT 5000
#define E1_N  20000
#define E2_N  20000
#define D_IN  64
#define D_H   64
#define D_EF  32

// Scratch (device globals — no allocations allowed)
__device__ float g_sum1[N_MID * D_H];   // layer-1 scatter sums, then normalized h_mid (in place)
__device__ float g_cnt1[N_MID];
__device__ float g_cnt2[N_OUT];

// ---------------- packed f32x2 helpers ----------------
__device__ __forceinline__ void ffma2(unsigned long long& d, unsigned long long a, unsigned long long b) {
    asm("fma.rn.f32x2 %0, %1, %2, %0;" : "+l"(d) : "l"(a), "l"(b));
}
__device__ __forceinline__ unsigned long long pack2(float x) {
    unsigned long long r;
    asm("mov.b64 %0, {%1, %1};" : "=l"(r) : "r"(__float_as_uint(x)));
    return r;
}

// ---------------- zero scratch + output ----------------
__global__ void zero_kernel(float* __restrict__ out) {
    int t = blockIdx.x * blockDim.x + threadIdx.x;
    if (t < N_MID * D_H) g_sum1[t] = 0.f;
    if (t < N_MID)       g_cnt1[t] = 0.f;
    if (t < N_OUT)       g_cnt2[t] = 0.f;
    if (t < N_OUT * D_H) out[t]    = 0.f;
}

// ---------------- degree counts (both layers) ----------------
__global__ void count_kernel(const int* __restrict__ dst1, const int* __restrict__ dst2) {
    int t = blockIdx.x * blockDim.x + threadIdx.x;
    if (t < E1_N)              atomicAdd(&g_cnt1[dst1[t]], 1.0f);
    else if (t < E1_N + E2_N)  atomicAdd(&g_cnt2[dst2[t - E1_N]], 1.0f);
}

// ---------------- fused edge kernel ----------------
// msg[e, o] = sum_i h[src[e], i] * ( b[i*64+o] + sum_f ef[e,f] * W[f, i*64+o] )
// CTA: 128 edges x 32 outputs (o-half by blockIdx.y). atomicAdd into accum[dst[e]].
template <int LAYER>
__global__ void __launch_bounds__(128, 4) edge_kernel(
    const float* __restrict__ hfeat_arg,   // layer1: in_feat; layer2: unused
    const float* __restrict__ efeat,       // [E, 32]
    const float* __restrict__ W,           // [32, 4096]
    const float* __restrict__ bias,        // [4096]
    const int*   __restrict__ src,
    const int*   __restrict__ dst,
    int E,
    float* __restrict__ accum_arg)         // layer2: d_out; layer1: unused
{
    __shared__ float hs[64 * 129];  // transposed: hs[i*129 + edge], conflict-free reads
    __shared__ float ws[33 * 36];   // per-i slice: rows f=0..31 of W, row 32 = bias; stride 36

    const float* hfeat = (LAYER == 1) ? hfeat_arg : g_sum1;
    float* accum       = (LAYER == 1) ? g_sum1    : accum_arg;

    const int tid = threadIdx.x;
    const int e0  = blockIdx.x * 128;
    const int o0  = blockIdx.y * 32;
    const int e   = e0 + tid;
    const bool act = (e < E);

    // edge features -> registers (vectorized)
    float ef[32];
    {
        const float4* p = reinterpret_cast<const float4*>(efeat + (size_t)(act ? e : 0) * 32);
#pragma unroll
        for (int k = 0; k < 8; k++) {
            float4 v = p[k];
            ef[4 * k + 0] = v.x; ef[4 * k + 1] = v.y;
            ef[4 * k + 2] = v.z; ef[4 * k + 3] = v.w;
        }
    }

    // cooperative gather of source-node features, transposed into hs
#pragma unroll
    for (int k = 0; k < 16; k++) {
        int j  = tid + k * 128;      // 0..2047
        int r  = j >> 4;             // edge row within tile
        int c4 = j & 15;             // float4 index along feature dim
        int s  = (e0 + r < E) ? src[e0 + r] : 0;
        float4 v = reinterpret_cast<const float4*>(hfeat + (size_t)s * 64)[c4];
        int i = c4 * 4;
        hs[(i + 0) * 129 + r] = v.x;
        hs[(i + 1) * 129 + r] = v.y;
        hs[(i + 2) * 129 + r] = v.z;
        hs[(i + 3) * 129 + r] = v.w;
    }

    unsigned long long acc[16];
#pragma unroll
    for (int k = 0; k < 16; k++) acc[k] = 0ull;

    for (int i = 0; i < 64; i++) {
        __syncthreads();
        // stage W[:, i*64+o0 .. +31] and bias row (33 rows x 32 floats)
#pragma unroll
        for (int k = 0; k < 3; k++) {
            int j = tid + k * 128;
            if (j < 264) {
                int row = j >> 3, c4 = j & 7;
                float4 v;
                if (row < 32) v = reinterpret_cast<const float4*>(W + (size_t)row * 4096 + i * 64 + o0)[c4];
                else          v = reinterpret_cast<const float4*>(bias + i * 64 + o0)[c4];
                *reinterpret_cast<float4*>(&ws[row * 36 + c4 * 4]) = v;
            }
        }
        __syncthreads();

        float hi = hs[i * 129 + tid];

        unsigned long long t[16];
#pragma unroll
        for (int k = 0; k < 16; k++)
            t[k] = *reinterpret_cast<const unsigned long long*>(&ws[32 * 36 + 2 * k]);

#pragma unroll
        for (int f = 0; f < 32; f++) {
            unsigned long long efp = pack2(ef[f]);
            const float* wrow = &ws[f * 36];
#pragma unroll
            for (int k2 = 0; k2 < 8; k2++) {
                ulonglong2 w = *reinterpret_cast<const ulonglong2*>(wrow + 4 * k2);  // LDS.128 -> 2x b64
                ffma2(t[2 * k2 + 0], w.x, efp);
                ffma2(t[2 * k2 + 1], w.y, efp);
            }
        }

        unsigned long long hip = pack2(hi);
#pragma unroll
        for (int k = 0; k < 16; k++) ffma2(acc[k], t[k], hip);
    }

    if (act) {
        float* outp = accum + (size_t)dst[e] * 64 + o0;
#pragma unroll
        for (int k = 0; k < 16; k++) {
            float2 v = *reinterpret_cast<float2*>(&acc[k]);
            atomicAdd(outp + 2 * k + 0, v.x);
            atomicAdd(outp + 2 * k + 1, v.y);
        }
    }
}

// ---------------- normalize (mean) kernels ----------------
__global__ void normalize1_kernel() {
    int t = blockIdx.x * blockDim.x + threadIdx.x;
    if (t >= N_MID * D_H) return;
    float c = g_cnt1[t >> 6];
    float v = g_sum1[t] / fmaxf(c, 1.0f);
    g_sum1[t] = fmaxf(v, 0.0f);   // relu
}

__global__ void normalize2_kernel(float* __restrict__ out) {
    int t = blockIdx.x * blockDim.x + threadIdx.x;
    if (t >= N_OUT * D_H) return;
    float c = g_cnt2[t >> 6];
    out[t] = out[t] / fmaxf(c, 1.0f);
}

// ---------------- launch ----------------
extern "C" void kernel_launch(void* const* d_in, const int* in_sizes, int n_in,
                              void* d_out, int out_size) {
    const float* in_feat = (const float*)d_in[0];
    const float* ef1     = (const float*)d_in[1];
    const float* ef2     = (const float*)d_in[2];
    const float* W1      = (const float*)d_in[3];
    const float* b1      = (const float*)d_in[4];
    const float* W2      = (const float*)d_in[5];
    const float* b2      = (const float*)d_in[6];
    const int*   src1    = (const int*)d_in[7];
    const int*   dst1    = (const int*)d_in[8];
    const int*   src2    = (const int*)d_in[9];
    const int*   dst2    = (const int*)d_in[10];
    float* out = (float*)d_out;

    zero_kernel<<<(N_MID * D_H + 255) / 256, 256>>>(out);
    count_kernel<<<(E1_N + E2_N + 255) / 256, 256>>>(dst1, dst2);

    dim3 egrid1((E1_N + 127) / 128, 2);
    edge_kernel<1><<<egrid1, 128>>>(in_feat, ef1, W1, b1, src1, dst1, E1_N, nullptr);
    normalize1_kernel<<<(N_MID * D_H + 255) / 256, 256>>>();

    dim3 egrid2((E2_N + 127) / 128, 2);
    edge_kernel<2><<<egrid2, 128>>>(nullptr, ef2, W2, b2, src2, dst2, E2_N, out);
    normalize2_kernel<<<(N_OUT * D_H + 255) / 256, 256>>>(out);
}